// round 11
// baseline (speedup 1.0000x reference)
#include <cuda_runtime.h>

// QuantumLayer collapses analytically to out[b] = cos(x[b,0] + weights[0]):
//  - RY(w)RY(x)|0> = RY(x+w)|0> (angles add; product state).
//  - Qubit 0 is only ever a CNOT control; Z_0 commutes with the chain.
//  - <Z_0> = cos(x[b,0] + w[0]).
//
// R8 finding: scalar LDG / vector LDG / MLP-8 / TMA all hit the same
// ~1.5 TB/s DRAM wall => limiter is in the memory system, not the SM.
// This round's single change vs the best kernel (R7): add the .L2::256B
// prefetch-size modifier so each L2 miss fills 256B (2 full lines, all
// needed) instead of a 32B sector -> 32x fewer DRAM fill transactions.

__global__ __launch_bounds__(256)
void quantum_layer_kernel(const float* __restrict__ x,
                          const float* __restrict__ w,
                          float* __restrict__ out,
                          int B)
{
    const float w0 = __ldg(w);
    const int t      = blockIdx.x * 256 + threadIdx.x;
    const int stride = gridDim.x * 256;          // 151552 for B=262144
    const int i1     = t + stride;

    unsigned r0, r1;
    // front-batch both 256-bit row loads (MLP_p1 = 2), L2-sticky,
    // 256B DRAM-fill promotion
    asm volatile("{.reg .b32 t1,t2,t3,t4,t5,t6,t7;\n\t"
                 "ld.global.nc.L2::evict_last.L2::256B.v8.b32 "
                 "{%0,t1,t2,t3,t4,t5,t6,t7}, [%1];}"
                 : "=r"(r0) : "l"(x + (size_t)t * 8));
    const bool has1 = (i1 < B);
    if (has1) {
        asm volatile("{.reg .b32 t1,t2,t3,t4,t5,t6,t7;\n\t"
                     "ld.global.nc.L2::evict_last.L2::256B.v8.b32 "
                     "{%0,t1,t2,t3,t4,t5,t6,t7}, [%1];}"
                     : "=r"(r1) : "l"(x + (size_t)i1 * 8));
    }

    out[t] = __cosf(__uint_as_float(r0) + w0);
    if (has1) {
        out[i1] = __cosf(__uint_as_float(r1) + w0);
    }
}

extern "C" void kernel_launch(void* const* d_in, const int* in_sizes, int n_in,
                              void* d_out, int out_size)
{
    const float* x = (const float*)d_in[0];   // [B, 8] float32
    const float* w = (const float*)d_in[1];   // [8]   float32
    float* out = (float*)d_out;               // [B]   float32
    int B = out_size;

    // 592 = 4 * 148: exactly 4 CTAs per SM, zero wave quantization.
    quantum_layer_kernel<<<592, 256>>>(x, w, out, B);
}

// round 12
// speedup vs baseline: 1.0337x; 1.0337x over previous
#include <cuda_runtime.h>

// QuantumLayer collapses analytically to out[b] = cos(x[b,0] + weights[0]):
//  - RY(w)RY(x)|0> = RY(x+w)|0> (angles add; product state).
//  - Qubit 0 is only ever a CNOT control; Z_0 commutes with the chain.
//  - <Z_0> = cos(x[b,0] + w[0]).
//
// R11 conclusion: all fetch mechanisms / cache policies / MLP shapes land at
// 5.38-6.2us; L2-warm harness replays match DRAM-cold ncu replays => time is
// a latency/launch/clock floor, not bandwidth. This round: the minimal
// kernel. 1024 CTAs x 256 thr x 1 row = 262144 exact -> zero predicates,
// zero dead registers, straight-line LDG -> FADD -> MUFU(cos) -> STG.
// Default caching so the harness's warm replays hit L1/L2 naturally.

__global__ __launch_bounds__(256)
void quantum_layer_kernel(const float* __restrict__ x,
                          const float* __restrict__ w,
                          float* __restrict__ out)
{
    const int b = blockIdx.x * 256 + threadIdx.x;   // exact cover, no check
    const float a  = __ldg(x + (size_t)b * 8);      // one 32B row-sector
    const float w0 = __ldg(w);                       // broadcast, cache-hit
    out[b] = __cosf(a + w0);
}

// Safety fallback for unexpected sizes (not hit for B=262144).
__global__ __launch_bounds__(256)
void quantum_layer_scalar(const float* __restrict__ x,
                          const float* __restrict__ w,
                          float* __restrict__ out, int B)
{
    const float w0 = __ldg(w);
    int b = blockIdx.x * blockDim.x + threadIdx.x;
    if (b < B) out[b] = __cosf(__ldg(x + (size_t)b * 8) + w0);
}

extern "C" void kernel_launch(void* const* d_in, const int* in_sizes, int n_in,
                              void* d_out, int out_size)
{
    const float* x = (const float*)d_in[0];   // [B, 8] float32
    const float* w = (const float*)d_in[1];   // [8]   float32
    float* out = (float*)d_out;               // [B]   float32
    int B = out_size;

    if ((B & 255) == 0) {
        quantum_layer_kernel<<<B / 256, 256>>>(x, w, out);   // 1024 CTAs
    } else {
        quantum_layer_scalar<<<(B + 255) / 256, 256>>>(x, w, out, B);
    }
}